// round 3
// baseline (speedup 1.0000x reference)
#include <cuda_runtime.h>
#include <math.h>

#define BB 8
#define NHEADS 16
#define DH 48
#define DD 768
#define P2 256

typedef unsigned long long ull;

// ---- f32x2 packed helpers (Blackwell FFMA2) ----
__device__ __forceinline__ ull pk2(float lo, float hi) {
    ull r; asm("mov.b64 %0,{%1,%2};" : "=l"(r) : "f"(lo), "f"(hi)); return r;
}
__device__ __forceinline__ ull dup2(float v) {
    ull r; asm("mov.b64 %0,{%1,%1};" : "=l"(r) : "f"(v)); return r;
}
__device__ __forceinline__ void fma2(ull& d, ull a, ull b) {
    asm("fma.rn.f32x2 %0,%1,%2,%0;" : "+l"(d) : "l"(a), "l"(b));
}
__device__ __forceinline__ float2 up2(ull v) {
    float2 r; asm("mov.b64 {%0,%1},%2;" : "=f"(r.x), "=f"(r.y) : "l"(v)); return r;
}

// Scratch: windowified Q/K/V  [b][head][n][pix4][dh]  (25MB each)
__device__ float g_Q[BB*NHEADS*P2*4*DH];
__device__ float g_K[BB*NHEADS*P2*4*DH];
__device__ float g_V[BB*NHEADS*P2*4*DH];

// ---------------------------------------------------------------------------
// Fused BN-fold + depthwise 5x5 conv for q,k,v (q pre-scaled by d^-0.5).
// x: (b, 1024, 768) channels-last. Output written windowified:
//   image pixel (r,cl): n = (r%16)*16 + (cl%16), pix = (r/16)*2 + (cl/16)
// Block: 256 thr = 32 channels x 8 slots. Grid: (24 chunks * 4 rowquads, 8 b).
// Each thread: 4 groups of (1 row x 8 cols), 3 convs fused, f32x2 packed math.
// ---------------------------------------------------------------------------
__global__ __launch_bounds__(256) void conv_kernel(const float* __restrict__ x,
                                                   const float* __restrict__ conv_w,
                                                   const float* __restrict__ gamma,
                                                   const float* __restrict__ beta,
                                                   const float* __restrict__ mean,
                                                   const float* __restrict__ var) {
    __shared__ float winv[3][32];
    __shared__ float wbs[3][32];
    __shared__ float wraw[3][32][25];

    int b     = blockIdx.y;
    int chunk = blockIdx.x >> 2;
    int rquad = blockIdx.x & 3;
    int lane5 = threadIdx.x & 31;
    int slot  = threadIdx.x >> 5;
    int c0    = chunk * 32;
    int c     = c0 + lane5;
    int head  = c / DH;
    int cc    = c % DH;

    // ---- stage BN params + raw weights cooperatively ----
    if (threadIdx.x < 96) {
        int j  = threadIdx.x / 32;
        int cl = threadIdx.x % 32;
        int t  = j * DD + c0 + cl;
        float inv = gamma[t] * rsqrtf(var[t] + 1e-5f);
        float bs  = beta[t] - mean[t] * inv;
        if (j == 0) { inv *= 0.03608439182435161f; bs *= 0.03608439182435161f; } // 768^-0.5
        winv[j][cl] = inv;
        wbs[j][cl]  = bs;
    }
    for (int f = threadIdx.x; f < 3 * 800; f += 256) {
        int j = f / 800, rem = f % 800;
        (&wraw[0][0][0])[j * 800 + rem] = conv_w[(size_t)(j * DD + c0) * 25 + rem];
    }
    __syncthreads();

    // ---- per-thread folded weights in registers ----
    float w[3][25];
    ull biasd[3];
#pragma unroll
    for (int j = 0; j < 3; j++) {
        float inv = winv[j][lane5];
        biasd[j] = dup2(wbs[j][lane5]);
#pragma unroll
        for (int tp = 0; tp < 25; tp++) w[j][tp] = wraw[j][lane5][tp] * inv;
    }

    const float* xb = x + (size_t)b * 1024 * DD + c;

#pragma unroll 1
    for (int gi = 0; gi < 4; gi++) {
        int g    = slot * 4 + gi;       // 0..31
        int row  = rquad * 8 + (g >> 2);
        int col0 = (g & 3) * 8;

        // acc pairs: outputs (0,1),(2,3),(4,5),(6,7); init = bias (folds the add)
        ull acc[3][4];
#pragma unroll
        for (int j = 0; j < 3; j++)
#pragma unroll
            for (int p = 0; p < 4; p++) acc[j][p] = biasd[j];

#pragma unroll
        for (int dy = 0; dy < 5; dy++) {
            int r = row + dy - 2;
            if ((unsigned)r < 32u) {
                const float* xr = xb + (size_t)(r * 32) * DD;
                float xv[12];
#pragma unroll
                for (int i = 0; i < 12; i++) {
                    int cl = col0 + i - 2;
                    xv[i] = ((unsigned)cl < 32u) ? xr[cl * DD] : 0.f;
                }
                ull xp[11];
#pragma unroll
                for (int i = 0; i < 11; i++) xp[i] = pk2(xv[i], xv[i + 1]);
#pragma unroll
                for (int j = 0; j < 3; j++) {
#pragma unroll
                    for (int dx = 0; dx < 5; dx++) {
                        ull wd = dup2(w[j][dy * 5 + dx]);
                        fma2(acc[j][0], wd, xp[dx + 0]);
                        fma2(acc[j][1], wd, xp[dx + 2]);
                        fma2(acc[j][2], wd, xp[dx + 4]);
                        fma2(acc[j][3], wd, xp[dx + 6]);
                    }
                }
            }
        }

        // col group never crosses the 16-boundary (col0 in {0,8,16,24})
        int pix   = ((row >> 4) << 1) + (col0 >> 4);
        int nbase = (row & 15) * 16 + (col0 & 15);
        int obase = (((b * NHEADS + head) * P2 + nbase) * 4 + pix) * DH + cc;
#pragma unroll
        for (int p = 0; p < 4; p++) {
            float2 aq = up2(acc[0][p]);
            float2 ak = up2(acc[1][p]);
            float2 av = up2(acc[2][p]);
            int off0 = obase + (2 * p) * (4 * DH);
            int off1 = off0 + 4 * DH;
            g_Q[off0] = aq.x;  g_Q[off1] = aq.y;
            g_K[off0] = ak.x;  g_K[off1] = ak.y;
            g_V[off0] = av.x;  g_V[off1] = av.y;
        }
    }
}

// ---------------------------------------------------------------------------
// Fused top-8 + sparse window attention. One warp per (b, head, window n).
// ---------------------------------------------------------------------------
struct WarpSmem {
    float vbuf[32 * 52 + 64];  // v staged, stride 52 (conflict-free + f4-aligned)
    float qs[4 * 48];          // q (already scaled by conv)
    float at[128];             // softmax weights, [kk][qp] (float4 per kk)
};

__global__ __launch_bounds__(128) void attn_kernel(const float* __restrict__ adj,
                                                   float* __restrict__ out) {
    __shared__ __align__(16) WarpSmem sm[4];
    const unsigned FULL = 0xffffffffu;
    int warp = threadIdx.x >> 5;
    int lane = threadIdx.x & 31;
    int widx = blockIdx.x * 4 + warp;      // 0..32767
    int bh   = widx >> 8;
    int n    = widx & 255;
    int b    = bh >> 4;
    int head = bh & 15;
    WarpSmem& S = sm[warp];

    // ---- top-8 of gen_adj row (256 values, 8 per lane) ----
    const float* rowp = adj + ((size_t)bh * 256 + n) * 256;
    float vals[8];
#pragma unroll
    for (int j = 0; j < 8; j++) vals[j] = rowp[j * 32 + lane];

    int mysel = 0;
    for (int it = 0; it < 8; it++) {
        float bv = -1e30f;
        int bi = 0;
#pragma unroll
        for (int j = 0; j < 8; j++)
            if (vals[j] > bv) { bv = vals[j]; bi = j * 32 + lane; }
#pragma unroll
        for (int off = 16; off > 0; off >>= 1) {
            float ov = __shfl_down_sync(FULL, bv, off);
            int   oi = __shfl_down_sync(FULL, bi, off);
            if (ov > bv) { bv = ov; bi = oi; }
        }
        bi = __shfl_sync(FULL, bi, 0);
        if (lane == it) mysel = bi;
#pragma unroll
        for (int j = 0; j < 8; j++)
            if (bi == j * 32 + lane) vals[j] = -1e30f;
    }

    // ---- stage q into smem (pre-scaled by conv) ----
    {
        const float4* qsrc = (const float4*)(g_Q + (size_t)widx * 192);
        ((float4*)S.qs)[lane] = qsrc[lane];
        if (lane < 16) ((float4*)S.qs)[32 + lane] = qsrc[32 + lane];
    }

    // ---- gather: lane kk = sel*4 + pix. k -> reg pairs, v -> smem ----
    int sel  = __shfl_sync(FULL, mysel, lane >> 2);
    int base = ((bh * 256 + sel) * 4 + (lane & 3)) * DH;
    ull k2[24];
    {
        const float4* kp = (const float4*)(g_K + base);
#pragma unroll
        for (int i = 0; i < 12; i++) {
            float4 t = kp[i];
            k2[2*i]   = pk2(t.x, t.y);
            k2[2*i+1] = pk2(t.z, t.w);
        }
        const float4* vp = (const float4*)(g_V + base);
        float4* vd = (float4*)(&S.vbuf[lane * 52]);
#pragma unroll
        for (int i = 0; i < 12; i++) vd[i] = vp[i];
    }
    __syncwarp();

    // ---- logits[qp] for this lane's key column (packed dot over 48) ----
    ull l2[4] = {0ull, 0ull, 0ull, 0ull};
#pragma unroll
    for (int ch = 0; ch < 12; ch++) {
#pragma unroll
        for (int qp = 0; qp < 4; qp++) {
            float4 qv = ((const float4*)&S.qs[qp * 48])[ch];   // broadcast LDS.128
            fma2(l2[qp], pk2(qv.x, qv.y), k2[2*ch]);
            fma2(l2[qp], pk2(qv.z, qv.w), k2[2*ch+1]);
        }
    }
    float l[4];
#pragma unroll
    for (int qp = 0; qp < 4; qp++) { float2 h = up2(l2[qp]); l[qp] = h.x + h.y; }

    // ---- softmax across 32 lanes per qp-row ----
    float a[4];
#pragma unroll
    for (int qp = 0; qp < 4; qp++) {
        float m = l[qp];
#pragma unroll
        for (int off = 16; off > 0; off >>= 1)
            m = fmaxf(m, __shfl_xor_sync(FULL, m, off));
        float e = __expf(l[qp] - m);
        float s = e;
#pragma unroll
        for (int off = 16; off > 0; off >>= 1)
            s += __shfl_xor_sync(FULL, s, off);
        a[qp] = __fdividef(e, s);
    }
    ((float4*)S.at)[lane] = make_float4(a[0], a[1], a[2], a[3]);
    __syncwarp();

    // ---- out[qp][c] = sum_kk a[qp][kk] * v[kk][c]; packed over qp pairs ----
    ull o1a = 0ull, o1b = 0ull, o2a = 0ull, o2b = 0ull;
#pragma unroll
    for (int kk = 0; kk < 32; kk++) {
        float4 av = ((const float4*)S.at)[kk];          // broadcast
        float v1 = S.vbuf[kk * 52 + lane];
        float v2 = S.vbuf[kk * 52 + 32 + lane];         // garbage for lane>=16, never stored
        ull axy = pk2(av.x, av.y), azw = pk2(av.z, av.w);
        ull v1d = dup2(v1), v2d = dup2(v2);
        fma2(o1a, axy, v1d);
        fma2(o1b, azw, v1d);
        fma2(o2a, axy, v2d);
        fma2(o2b, azw, v2d);
    }
    float2 p1a = up2(o1a), p1b = up2(o1b), p2a = up2(o2a), p2b = up2(o2b);
    float o1[4] = {p1a.x, p1a.y, p1b.x, p1b.y};
    float o2[4] = {p2a.x, p2a.y, p2b.x, p2b.y};

    // ---- scatter to output: row = (p&1)*16 + wy, col = (p>>1)*16 + wx ----
    int wy = n >> 4, wx = n & 15;
    float* ob = out + (size_t)b * 1024 * 768 + head * 48;
#pragma unroll
    for (int p = 0; p < 4; p++) {
        int row = ((p & 1) << 4) + wy;
        int col = ((p >> 1) << 4) + wx;
        int off = (row * 32 + col) * 768;
        ob[off + lane] = o1[p];
        if (lane < 16) ob[off + 32 + lane] = o2[p];
    }
}

// ---------------------------------------------------------------------------
extern "C" void kernel_launch(void* const* d_in, const int* in_sizes, int n_in,
                              void* d_out, int out_size) {
    const float* x      = (const float*)d_in[0];
    // d_in[1] = noise (unused by reference)
    const float* adj    = (const float*)d_in[2];
    const float* conv_w = (const float*)d_in[3];
    const float* gamma  = (const float*)d_in[4];
    const float* beta   = (const float*)d_in[5];
    const float* mean   = (const float*)d_in[6];
    const float* var    = (const float*)d_in[7];
    // d_in[8] = sparsity (constant 8, compiled in)
    float* out = (float*)d_out;

    conv_kernel<<<dim3(96, 8), 256>>>(x, conv_w, gamma, beta, mean, var);
    attn_kernel<<<8192, 128>>>(adj, out);
}

// round 4
// speedup vs baseline: 1.5480x; 1.5480x over previous
#include <cuda_runtime.h>
#include <math.h>

#define BB 8
#define NHEADS 16
#define DH 48
#define DD 768
#define P2 256

typedef unsigned long long ull;

// ---- f32x2 packed helpers (Blackwell FFMA2) ----
__device__ __forceinline__ ull pk2(float lo, float hi) {
    ull r; asm("mov.b64 %0,{%1,%2};" : "=l"(r) : "f"(lo), "f"(hi)); return r;
}
__device__ __forceinline__ ull dup2(float v) {
    ull r; asm("mov.b64 %0,{%1,%1};" : "=l"(r) : "f"(v)); return r;
}
__device__ __forceinline__ void fma2(ull& d, ull a, ull b) {
    asm("fma.rn.f32x2 %0,%1,%2,%0;" : "+l"(d) : "l"(a), "l"(b));
}
__device__ __forceinline__ float2 up2(ull v) {
    float2 r; asm("mov.b64 {%0,%1},%2;" : "=f"(r.x), "=f"(r.y) : "l"(v)); return r;
}

// Scratch: windowified Q/K/V  [b][head][n][pix4][dh]  (25MB each)
__device__ float g_Q[BB*NHEADS*P2*4*DH];
__device__ float g_K[BB*NHEADS*P2*4*DH];
__device__ float g_V[BB*NHEADS*P2*4*DH];

// ---------------------------------------------------------------------------
// Fused BN-fold + depthwise 5x5 conv for q,k,v (q pre-scaled by d^-0.5).
// Block: 128 thr = 32 channels x 4 slots. Grid: (24 chunks * 4 rowquads, 8 b).
// Folded weights pre-duplicated (f32x2) in SMEM; inner loop = LDS.64 + FFMA2.
// Output windowified: pixel (r,cl) -> n=(r%16)*16+(cl%16), pix=(r/16)*2+(cl/16)
// ---------------------------------------------------------------------------
__global__ __launch_bounds__(128) void conv_kernel(const float* __restrict__ x,
                                                   const float* __restrict__ conv_w,
                                                   const float* __restrict__ gamma,
                                                   const float* __restrict__ beta,
                                                   const float* __restrict__ mean,
                                                   const float* __restrict__ var) {
    __shared__ ull  wdup[3][25][32];   // folded weights, duplicated to both halves
    __shared__ ull  bdup[3][32];
    __shared__ float sinv[3][32];

    int tid   = threadIdx.x;
    int b     = blockIdx.y;
    int chunk = blockIdx.x >> 2;
    int rquad = blockIdx.x & 3;
    int lane5 = tid & 31;
    int slot  = tid >> 5;             // 0..3
    int c0    = chunk * 32;
    int c     = c0 + lane5;

    // ---- prologue: fold BN, duplicate, stage to smem ----
    if (tid < 96) {
        int j  = tid / 32;
        int cl = tid % 32;
        int t  = j * DD + c0 + cl;
        float inv = gamma[t] * rsqrtf(var[t] + 1e-5f);
        float bs  = beta[t] - mean[t] * inv;
        if (j == 0) { inv *= 0.03608439182435161f; bs *= 0.03608439182435161f; } // 768^-0.5
        sinv[j][cl] = inv;
        bdup[j][cl] = dup2(bs);
    }
    __syncthreads();
    for (int f = tid; f < 3 * 800; f += 128) {
        int j   = f / 800;
        int rem = f - j * 800;
        int ch  = rem / 25;
        int tap = rem - ch * 25;
        float wv = conv_w[(size_t)(j * DD + c0 + ch) * 25 + tap] * sinv[j][ch];
        wdup[j][tap][ch] = dup2(wv);
    }
    __syncthreads();

    ull biasr[3];
#pragma unroll
    for (int j = 0; j < 3; j++) biasr[j] = bdup[j][lane5];

    const float* xb = x + (size_t)b * 1024 * DD + c;

#pragma unroll 1
    for (int gi = 0; gi < 8; gi++) {
        int g    = slot * 8 + gi;       // 0..31
        int row  = rquad * 8 + (g >> 2);
        int col0 = (g & 3) * 8;

        ull acc[3][4];
#pragma unroll
        for (int j = 0; j < 3; j++)
#pragma unroll
            for (int p = 0; p < 4; p++) acc[j][p] = biasr[j];

#pragma unroll
        for (int dy = 0; dy < 5; dy++) {
            int r = row + dy - 2;
            if ((unsigned)r < 32u) {
                const float* xr = xb + (size_t)(r * 32) * DD;
                float xv[12];
#pragma unroll
                for (int i = 0; i < 12; i++) {
                    int cl = col0 + i - 2;
                    xv[i] = ((unsigned)cl < 32u) ? xr[cl * DD] : 0.f;
                }
                ull xp[11];
#pragma unroll
                for (int i = 0; i < 11; i++) xp[i] = pk2(xv[i], xv[i + 1]);
#pragma unroll
                for (int j = 0; j < 3; j++) {
#pragma unroll
                    for (int dx = 0; dx < 5; dx++) {
                        ull wd = wdup[j][dy * 5 + dx][lane5];   // LDS.64
                        fma2(acc[j][0], wd, xp[dx + 0]);
                        fma2(acc[j][1], wd, xp[dx + 2]);
                        fma2(acc[j][2], wd, xp[dx + 4]);
                        fma2(acc[j][3], wd, xp[dx + 6]);
                    }
                }
            }
        }

        int head  = c / DH;
        int cc    = c % DH;
        int pix   = ((row >> 4) << 1) + (col0 >> 4);
        int nbase = (row & 15) * 16 + (col0 & 15);
        int obase = (((b * NHEADS + head) * P2 + nbase) * 4 + pix) * DH + cc;
#pragma unroll
        for (int p = 0; p < 4; p++) {
            float2 aq = up2(acc[0][p]);
            float2 ak = up2(acc[1][p]);
            float2 av = up2(acc[2][p]);
            int off0 = obase + (2 * p) * (4 * DH);
            int off1 = off0 + 4 * DH;
            g_Q[off0] = aq.x;  g_Q[off1] = aq.y;
            g_K[off0] = ak.x;  g_K[off1] = ak.y;
            g_V[off0] = av.x;  g_V[off1] = av.y;
        }
    }
}

// ---------------------------------------------------------------------------
// Fused top-8 + sparse window attention. One warp per (b, head, window n).
// Coalesced K/V gather: 4-lane groups load contiguous 768B runs; K staged in
// smem (stride-52 pad, conflict-free), reloaded to regs; SAME buffer reused
// for V (halves smem). All math scalar fp32.
// ---------------------------------------------------------------------------
struct WarpSmem {
    float buf[32 * 52];   // K stage, then V  (float4-aligned rows)
    float qs[4 * 48];     // q (pre-scaled by conv)
    float at[128];        // softmax weights [kk][qp]
};

__global__ __launch_bounds__(128) void attn_kernel(const float* __restrict__ adj,
                                                   float* __restrict__ out) {
    __shared__ __align__(16) WarpSmem sm[4];
    const unsigned FULL = 0xffffffffu;
    int warp = threadIdx.x >> 5;
    int lane = threadIdx.x & 31;
    int widx = blockIdx.x * 4 + warp;      // 0..32767
    int bh   = widx >> 8;
    int n    = widx & 255;
    int b    = bh >> 4;
    int head = bh & 15;
    int la3  = lane & 3;
    WarpSmem& S = sm[warp];

    // ---- stage q into smem early (overlap with top-k) ----
    {
        const float4* qsrc = (const float4*)(g_Q + (size_t)widx * 192);
        ((float4*)S.qs)[lane] = qsrc[lane];
        if (lane < 16) ((float4*)S.qs)[32 + lane] = qsrc[32 + lane];
    }

    // ---- top-8 of gen_adj row (256 values, 8 per lane) ----
    const float* rowp = adj + ((size_t)bh * 256 + n) * 256;
    float vals[8];
#pragma unroll
    for (int j = 0; j < 8; j++) vals[j] = rowp[j * 32 + lane];

    int mysel = 0;
    for (int it = 0; it < 8; it++) {
        float bv = -1e30f;
        int bi = 0;
#pragma unroll
        for (int j = 0; j < 8; j++)
            if (vals[j] > bv) { bv = vals[j]; bi = j * 32 + lane; }
#pragma unroll
        for (int off = 16; off > 0; off >>= 1) {
            float ov = __shfl_down_sync(FULL, bv, off);
            int   oi = __shfl_down_sync(FULL, bi, off);
            if (ov > bv) { bv = ov; bi = oi; }
        }
        bi = __shfl_sync(FULL, bi, 0);
        if (lane == it) mysel = bi;
#pragma unroll
        for (int j = 0; j < 8; j++)
            if (bi == j * 32 + lane) vals[j] = -1e30f;
    }

    // ---- coalesced K gather -> smem (padded), reload own column -> regs ----
    // 4-lane group g loads run g (= sel rank g): 48 float4 contiguous.
    int run   = lane >> 2;
    int sel   = __shfl_sync(FULL, mysel, run);
    const float4* kg = (const float4*)(g_K + ((size_t)(bh * 256 + sel) * 4) * DH);
    const float4* vg = (const float4*)(g_V + ((size_t)(bh * 256 + sel) * 4) * DH);
    float4* buf4 = (float4*)S.buf;

#pragma unroll
    for (int i = 0; i < 12; i++) {
        // q-index within run: 4*i + la3; pix = i/3 (compile-time), c4 = 4*(i%3)+la3
        float4 t = kg[4 * i + la3];
        buf4[(run * 4 + i / 3) * 13 + 4 * (i % 3) + la3] = t;
    }
    __syncwarp();

    float k[48];
#pragma unroll
    for (int i = 0; i < 12; i++) {
        float4 t = buf4[lane * 13 + i];
        k[4*i] = t.x; k[4*i+1] = t.y; k[4*i+2] = t.z; k[4*i+3] = t.w;
    }
    __syncwarp();

    // ---- coalesced V gather into the SAME buffer ----
#pragma unroll
    for (int i = 0; i < 12; i++) {
        float4 t = vg[4 * i + la3];
        buf4[(run * 4 + i / 3) * 13 + 4 * (i % 3) + la3] = t;
    }

    // ---- logits[qp] for this lane's key column (dot over 48) ----
    float l[4] = {0.f, 0.f, 0.f, 0.f};
#pragma unroll
    for (int ch = 0; ch < 12; ch++) {
#pragma unroll
        for (int qp = 0; qp < 4; qp++) {
            float4 qv = ((const float4*)&S.qs[qp * 48])[ch];   // broadcast LDS.128
            l[qp] += qv.x * k[4*ch] + qv.y * k[4*ch+1]
                   + qv.z * k[4*ch+2] + qv.w * k[4*ch+3];
        }
    }

    // ---- softmax across 32 lanes per qp-row ----
    float a[4];
#pragma unroll
    for (int qp = 0; qp < 4; qp++) {
        float m = l[qp];
#pragma unroll
        for (int off = 16; off > 0; off >>= 1)
            m = fmaxf(m, __shfl_xor_sync(FULL, m, off));
        float e = __expf(l[qp] - m);
        float s = e;
#pragma unroll
        for (int off = 16; off > 0; off >>= 1)
            s += __shfl_xor_sync(FULL, s, off);
        a[qp] = __fdividef(e, s);
    }
    ((float4*)S.at)[lane] = make_float4(a[0], a[1], a[2], a[3]);
    __syncwarp();

    // ---- out[qp][c] = sum_kk a[qp][kk] * v[kk][c] ----
    float o1[4] = {0,0,0,0}, o2[4] = {0,0,0,0};
#pragma unroll
    for (int kk = 0; kk < 32; kk++) {
        float4 av = ((const float4*)S.at)[kk];          // broadcast
        float v1 = S.buf[kk * 52 + lane];
        float v2 = S.buf[kk * 52 + 32 + lane];          // garbage for lane>=16, never stored
        o1[0] += av.x * v1; o1[1] += av.y * v1; o1[2] += av.z * v1; o1[3] += av.w * v1;
        o2[0] += av.x * v2; o2[1] += av.y * v2; o2[2] += av.z * v2; o2[3] += av.w * v2;
    }

    // ---- scatter to output: row = (p&1)*16 + wy, col = (p>>1)*16 + wx ----
    int wy = n >> 4, wx = n & 15;
    float* ob = out + (size_t)b * 1024 * 768 + head * 48;
#pragma unroll
    for (int p = 0; p < 4; p++) {
        int row = ((p & 1) << 4) + wy;
        int col = ((p >> 1) << 4) + wx;
        int off = (row * 32 + col) * 768;
        ob[off + lane] = o1[p];
        if (lane < 16) ob[off + 32 + lane] = o2[p];
    }
}

// ---------------------------------------------------------------------------
extern "C" void kernel_launch(void* const* d_in, const int* in_sizes, int n_in,
                              void* d_out, int out_size) {
    const float* x      = (const float*)d_in[0];
    // d_in[1] = noise (unused by reference)
    const float* adj    = (const float*)d_in[2];
    const float* conv_w = (const float*)d_in[3];
    const float* gamma  = (const float*)d_in[4];
    const float* beta   = (const float*)d_in[5];
    const float* mean   = (const float*)d_in[6];
    const float* var    = (const float*)d_in[7];
    // d_in[8] = sparsity (constant 8, compiled in)
    float* out = (float*)d_out;

    conv_kernel<<<dim3(96, 8), 128>>>(x, conv_w, gamma, beta, mean, var);
    attn_kernel<<<8192, 128>>>(adj, out);
}